// round 6
// baseline (speedup 1.0000x reference)
#include <cuda_runtime.h>
#include <cstdint>
#include <cstddef>

#define NNODES 100000
#define NEDGES 1600000
#define FIN 256
#define HID 64
#define CHUNK 4096
#define NCHUNK ((NNODES + CHUNK - 1) / CHUNK)

// ---------------- device scratch (no allocations allowed) ----------------
__device__ int   g_indeg[NNODES];
__device__ int   g_outdeg[NNODES];
__device__ int   g_rowptr[NNODES + 1];
__device__ int   g_cursor[NNODES];
__device__ int   g_srcsorted[NEDGES];
__device__ int   g_chunksum[NCHUNK];
__device__ float g_ns[NNODES];
__device__ float g_nd[NNODES];
__device__ float g_t[(size_t)NNODES * HID];     // t0 for layer 0, then A_l
__device__ float g_h0[(size_t)NNODES * HID];
__device__ float g_h1[(size_t)NNODES * HID];
__device__ float g_h2[(size_t)NNODES * HID];
__device__ float g_proj[(size_t)NNODES * HID];

// ---------------- packed f32x2 helpers ----------------
__device__ __forceinline__ void fma2(unsigned long long& d,
                                     unsigned long long a,
                                     unsigned long long b) {
    asm("fma.rn.f32x2 %0, %1, %2, %0;" : "+l"(d) : "l"(a), "l"(b));
}
__device__ __forceinline__ unsigned long long dup2(float b) {
    unsigned long long r;
    asm("mov.b64 %0, {%1, %1};" : "=l"(r) : "f"(b));
    return r;
}
__device__ __forceinline__ float2 unpk(unsigned long long v) {
    float2 r;
    asm("mov.b64 {%0, %1}, %2;" : "=f"(r.x), "=f"(r.y) : "l"(v));
    return r;
}

// ---------------- setup kernels ----------------
__global__ void zero_in_kernel(int n) {
    int i = blockIdx.x * blockDim.x + threadIdx.x;
    if (i < n) g_indeg[i] = 0;
}
__global__ void zero_out_kernel(int n) {
    int i = blockIdx.x * blockDim.x + threadIdx.x;
    if (i < n) g_outdeg[i] = 0;
}
__global__ void count_in_kernel(const int* __restrict__ dst, int e) {
    int i4 = (blockIdx.x * blockDim.x + threadIdx.x) * 4;
    if (i4 + 3 < e) {
        int4 d = *(const int4*)(dst + i4);
        atomicAdd(&g_indeg[d.x], 1);
        atomicAdd(&g_indeg[d.y], 1);
        atomicAdd(&g_indeg[d.z], 1);
        atomicAdd(&g_indeg[d.w], 1);
    } else {
        for (int i = i4; i < e; i++) atomicAdd(&g_indeg[dst[i]], 1);
    }
}
__global__ void count_out_kernel(const int* __restrict__ src, int e) {
    int i4 = (blockIdx.x * blockDim.x + threadIdx.x) * 4;
    if (i4 + 3 < e) {
        int4 s = *(const int4*)(src + i4);
        atomicAdd(&g_outdeg[s.x], 1);
        atomicAdd(&g_outdeg[s.y], 1);
        atomicAdd(&g_outdeg[s.z], 1);
        atomicAdd(&g_outdeg[s.w], 1);
    } else {
        for (int i = i4; i < e; i++) atomicAdd(&g_outdeg[src[i]], 1);
    }
}
__global__ void ns_kernel(int n) {
    int i = blockIdx.x * blockDim.x + threadIdx.x;
    if (i < n) g_ns[i] = rsqrtf(fmaxf((float)g_outdeg[i], 1.0f));
}

__global__ void __launch_bounds__(1024) chunksum_kernel(int n) {
    __shared__ int wsum[32];
    int tid = threadIdx.x;
    int base = blockIdx.x * CHUNK + tid * 4;
    int s = 0;
    #pragma unroll
    for (int j = 0; j < 4; j++) {
        int i = base + j;
        if (i < n) s += g_indeg[i];
    }
    #pragma unroll
    for (int d = 16; d > 0; d >>= 1) s += __shfl_down_sync(0xffffffffu, s, d);
    if ((tid & 31) == 0) wsum[tid >> 5] = s;
    __syncthreads();
    if (tid < 32) {
        int v = wsum[tid];
        #pragma unroll
        for (int d = 16; d > 0; d >>= 1) v += __shfl_down_sync(0xffffffffu, v, d);
        if (tid == 0) g_chunksum[blockIdx.x] = v;
    }
}

__global__ void __launch_bounds__(1024) rescan_kernel(int n) {
    __shared__ int wsum[32];
    __shared__ int s_chunkoff;
    int tid = threadIdx.x;
    if (tid < 32) {
        int v = (tid < NCHUNK) ? g_chunksum[tid] : 0;
        int before = (tid < (int)blockIdx.x) ? v : 0;
        int all = v;
        #pragma unroll
        for (int d = 16; d > 0; d >>= 1) {
            before += __shfl_down_sync(0xffffffffu, before, d);
            all    += __shfl_down_sync(0xffffffffu, all, d);
        }
        if (tid == 0) {
            s_chunkoff = before;
            if (blockIdx.x == 0) g_rowptr[n] = all;
        }
    }
    int base = blockIdx.x * CHUNK + tid * 4;
    int v[4];
    int s = 0;
    #pragma unroll
    for (int j = 0; j < 4; j++) {
        int i = base + j;
        v[j] = (i < n) ? g_indeg[i] : 0;
        s += v[j];
    }
    int x = s;
    #pragma unroll
    for (int d = 1; d < 32; d <<= 1) {
        int y = __shfl_up_sync(0xffffffffu, x, d);
        if ((tid & 31) >= d) x += y;
    }
    if ((tid & 31) == 31) wsum[tid >> 5] = x;
    __syncthreads();
    if (tid < 32) {
        int w = wsum[tid];
        #pragma unroll
        for (int d = 1; d < 32; d <<= 1) {
            int y = __shfl_up_sync(0xffffffffu, w, d);
            if (tid >= d) w += y;
        }
        wsum[tid] = w;
    }
    __syncthreads();
    int warpoff = (tid >= 32) ? wsum[(tid >> 5) - 1] : 0;
    int excl = s_chunkoff + warpoff + (x - s);
    #pragma unroll
    for (int j = 0; j < 4; j++) {
        int i = base + j;
        if (i < n) {
            g_rowptr[i] = excl;
            g_cursor[i] = excl;
            g_nd[i] = rsqrtf(fmaxf((float)v[j], 1.0f));
        }
        excl += v[j];
    }
}

__global__ void csr_kernel(const int* __restrict__ src, const int* __restrict__ dst, int e) {
    int i4 = (blockIdx.x * blockDim.x + threadIdx.x) * 4;
    if (i4 + 3 < e) {
        int4 d = *(const int4*)(dst + i4);
        int4 s = *(const int4*)(src + i4);
        g_srcsorted[atomicAdd(&g_cursor[d.x], 1)] = s.x;
        g_srcsorted[atomicAdd(&g_cursor[d.y], 1)] = s.y;
        g_srcsorted[atomicAdd(&g_cursor[d.z], 1)] = s.z;
        g_srcsorted[atomicAdd(&g_cursor[d.w], 1)] = s.w;
    } else {
        for (int i = i4; i < e; i++)
            g_srcsorted[atomicAdd(&g_cursor[dst[i]], 1)] = src[i];
    }
}

// ---------------- packed-f32x2 GEMM, row-paired accumulators ----------------
// C[rows x 64] = A[rows x K] @ B[K x 64], rows from rowbase
// mode 1: C = (beta ? C : 0) + A@B
// mode 2: C = relu(nd[row] * (A@B) + bias[col])
template <int K>
__global__ void __launch_bounds__(128, 4) gemm_pk(
    const float* __restrict__ A, int lda,
    const float* __restrict__ B,
    float* __restrict__ C,
    const float* __restrict__ bias,
    int mode, int beta, int rowbase, int n)
{
    constexpr int KC = 16;
    constexpr int AST = 128 + 4;
    __shared__ float As[KC][AST];
    __shared__ float Bs[KC][64 + 4];

    const int tid = threadIdx.x;
    const int tr = tid >> 3;
    const int tcv = tid & 7;
    const int row0 = rowbase + blockIdx.x * 128;

    unsigned long long acc[4][8];
    #pragma unroll
    for (int rp = 0; rp < 4; rp++)
        #pragma unroll
        for (int c = 0; c < 8; c++) acc[rp][c] = 0ULL;

    for (int kc = 0; kc < K; kc += KC) {
        #pragma unroll
        for (int i = 0; i < 4; i++) {
            int flat = tid + i * 128;
            int row = flat >> 2;
            int k4 = flat & 3;
            float4 v = make_float4(0.f, 0.f, 0.f, 0.f);
            int gr = row0 + row;
            if (gr < n) v = *(const float4*)(A + (size_t)gr * lda + kc + k4 * 4);
            As[k4 * 4 + 0][row] = v.x;
            As[k4 * 4 + 1][row] = v.y;
            As[k4 * 4 + 2][row] = v.z;
            As[k4 * 4 + 3][row] = v.w;
        }
        #pragma unroll
        for (int i = 0; i < 2; i++) {
            int flat = tid + i * 128;
            int k = flat >> 4;
            int c4 = flat & 15;
            *(float4*)&Bs[k][c4 * 4] = *(const float4*)(B + (size_t)(kc + k) * 64 + c4 * 4);
        }
        __syncthreads();

        #pragma unroll
        for (int k = 0; k < KC; k++) {
            ulonglong2 aA = *(const ulonglong2*)&As[k][tr * 8];
            ulonglong2 aB = *(const ulonglong2*)&As[k][tr * 8 + 4];
            unsigned long long ap[4] = {aA.x, aA.y, aB.x, aB.y};
            float4 b0 = *(const float4*)&Bs[k][tcv * 8];
            float4 b1 = *(const float4*)&Bs[k][tcv * 8 + 4];
            unsigned long long bd[8] = {dup2(b0.x), dup2(b0.y), dup2(b0.z), dup2(b0.w),
                                        dup2(b1.x), dup2(b1.y), dup2(b1.z), dup2(b1.w)};
            #pragma unroll
            for (int rp = 0; rp < 4; rp++)
                #pragma unroll
                for (int c = 0; c < 8; c++)
                    fma2(acc[rp][c], ap[rp], bd[c]);
        }
        __syncthreads();
    }

    float4 bb0 = make_float4(0.f, 0.f, 0.f, 0.f), bb1 = bb0;
    if (mode == 2) {
        bb0 = *(const float4*)(bias + tcv * 8);
        bb1 = *(const float4*)(bias + tcv * 8 + 4);
    }

    #pragma unroll
    for (int rp = 0; rp < 4; rp++) {
        float2 p[8];
        #pragma unroll
        for (int c = 0; c < 8; c++) p[c] = unpk(acc[rp][c]);
        #pragma unroll
        for (int half = 0; half < 2; half++) {
            int gr = row0 + tr * 8 + 2 * rp + half;
            if (gr >= n) continue;
            float4 v0, v1;
            if (half == 0) {
                v0 = make_float4(p[0].x, p[1].x, p[2].x, p[3].x);
                v1 = make_float4(p[4].x, p[5].x, p[6].x, p[7].x);
            } else {
                v0 = make_float4(p[0].y, p[1].y, p[2].y, p[3].y);
                v1 = make_float4(p[4].y, p[5].y, p[6].y, p[7].y);
            }
            float* cp = C + (size_t)gr * 64 + tcv * 8;
            if (mode == 2) {
                float ndv = g_nd[gr];
                v0.x = fmaxf(fmaf(v0.x, ndv, bb0.x), 0.f);
                v0.y = fmaxf(fmaf(v0.y, ndv, bb0.y), 0.f);
                v0.z = fmaxf(fmaf(v0.z, ndv, bb0.z), 0.f);
                v0.w = fmaxf(fmaf(v0.w, ndv, bb0.w), 0.f);
                v1.x = fmaxf(fmaf(v1.x, ndv, bb1.x), 0.f);
                v1.y = fmaxf(fmaf(v1.y, ndv, bb1.y), 0.f);
                v1.z = fmaxf(fmaf(v1.z, ndv, bb1.z), 0.f);
                v1.w = fmaxf(fmaf(v1.w, ndv, bb1.w), 0.f);
            } else if (beta) {
                float4 o0 = *(const float4*)cp;
                float4 o1 = *(const float4*)(cp + 4);
                v0.x += o0.x; v0.y += o0.y; v0.z += o0.z; v0.w += o0.w;
                v1.x += o1.x; v1.y += o1.y; v1.z += o1.z; v1.w += o1.w;
            }
            *(float4*)cp = v0;
            *(float4*)(cp + 4) = v1;
        }
    }
}

// ---------------- CSR gather-aggregate over nodes [nodebase, nlim) ----------
// EPI 0: raw weighted sum;  EPI 1: relu(nd*sum + bias);  EPI 2: sum + bias
template <bool NS, int EPI>
__global__ void __launch_bounds__(256) aggregate_kernel(
    const float* __restrict__ tin, float* __restrict__ hout,
    const float* __restrict__ bias, int nodebase, int nlim)
{
    int g = blockIdx.x * 256 + threadIdx.x;
    int node = nodebase + (g >> 4);
    int lane = g & 15;
    if (node >= nlim) return;
    int beg = g_rowptr[node];
    int end = g_rowptr[node + 1];
    float4 acc = make_float4(0.f, 0.f, 0.f, 0.f);

    int e = beg;
    for (; e + 4 <= end; e += 4) {
        int s0 = __ldg(&g_srcsorted[e + 0]);
        int s1 = __ldg(&g_srcsorted[e + 1]);
        int s2 = __ldg(&g_srcsorted[e + 2]);
        int s3 = __ldg(&g_srcsorted[e + 3]);
        float4 v0 = *(const float4*)(tin + (size_t)s0 * 64 + lane * 4);
        float4 v1 = *(const float4*)(tin + (size_t)s1 * 64 + lane * 4);
        float4 v2 = *(const float4*)(tin + (size_t)s2 * 64 + lane * 4);
        float4 v3 = *(const float4*)(tin + (size_t)s3 * 64 + lane * 4);
        if (NS) {
            float w0 = __ldg(&g_ns[s0]);
            float w1 = __ldg(&g_ns[s1]);
            float w2 = __ldg(&g_ns[s2]);
            float w3 = __ldg(&g_ns[s3]);
            acc.x = fmaf(v0.x, w0, acc.x); acc.y = fmaf(v0.y, w0, acc.y);
            acc.z = fmaf(v0.z, w0, acc.z); acc.w = fmaf(v0.w, w0, acc.w);
            acc.x = fmaf(v1.x, w1, acc.x); acc.y = fmaf(v1.y, w1, acc.y);
            acc.z = fmaf(v1.z, w1, acc.z); acc.w = fmaf(v1.w, w1, acc.w);
            acc.x = fmaf(v2.x, w2, acc.x); acc.y = fmaf(v2.y, w2, acc.y);
            acc.z = fmaf(v2.z, w2, acc.z); acc.w = fmaf(v2.w, w2, acc.w);
            acc.x = fmaf(v3.x, w3, acc.x); acc.y = fmaf(v3.y, w3, acc.y);
            acc.z = fmaf(v3.w * 0.f + v3.z, w3, acc.z); acc.w = fmaf(v3.w, w3, acc.w);
        } else {
            acc.x += v0.x + v1.x + v2.x + v3.x;
            acc.y += v0.y + v1.y + v2.y + v3.y;
            acc.z += v0.z + v1.z + v2.z + v3.z;
            acc.w += v0.w + v1.w + v2.w + v3.w;
        }
    }
    for (; e < end; e++) {
        int s = __ldg(&g_srcsorted[e]);
        float4 v = *(const float4*)(tin + (size_t)s * 64 + lane * 4);
        if (NS) {
            float w = __ldg(&g_ns[s]);
            acc.x = fmaf(v.x, w, acc.x); acc.y = fmaf(v.y, w, acc.y);
            acc.z = fmaf(v.z, w, acc.z); acc.w = fmaf(v.w, w, acc.w);
        } else {
            acc.x += v.x; acc.y += v.y; acc.z += v.z; acc.w += v.w;
        }
    }

    float4 o = acc;
    if (EPI == 1) {
        float4 bb = *(const float4*)(bias + lane * 4);
        float ndv = g_nd[node];
        o.x = fmaxf(fmaf(acc.x, ndv, bb.x), 0.f);
        o.y = fmaxf(fmaf(acc.y, ndv, bb.y), 0.f);
        o.z = fmaxf(fmaf(acc.z, ndv, bb.z), 0.f);
        o.w = fmaxf(fmaf(acc.w, ndv, bb.w), 0.f);
    } else if (EPI == 2) {
        float4 bb = *(const float4*)(bias + lane * 4);
        o.x = acc.x + bb.x; o.y = acc.y + bb.y;
        o.z = acc.z + bb.z; o.w = acc.w + bb.w;
    }
    *(float4*)(hout + (size_t)node * 64 + lane * 4) = o;
}

// ---------------- host ----------------
extern "C" void kernel_launch(void* const* d_in, const int* in_sizes, int n_in,
                              void* d_out, int out_size)
{
    const float* feats = (const float*)d_in[0];
    const int*   src   = (const int*)d_in[1];
    const int*   dst   = (const int*)d_in[2];
    const float* W[5];
    const float* b[5];
    for (int i = 0; i < 5; i++) {
        W[i] = (const float*)d_in[3 + 2 * i];
        b[i] = (const float*)d_in[4 + 2 * i];
    }
    const float* Wout = (const float*)d_in[13];
    const float* bout = (const float*)d_in[14];
    float* out = (float*)d_out;

    int n = in_sizes[0] / FIN;   // 100000
    int e = in_sizes[1];         // 1600000

    float *A, *proj, *hb[3];
    cudaGetSymbolAddress((void**)&A, g_t);
    cudaGetSymbolAddress((void**)&proj, g_proj);
    cudaGetSymbolAddress((void**)&hb[0], g_h0);
    cudaGetSymbolAddress((void**)&hb[1], g_h1);
    cudaGetSymbolAddress((void**)&hb[2], g_h2);

    static cudaStream_t side = nullptr, s2 = nullptr;
    static cudaEvent_t evFork, evPre, evH[6], evP[6], evA0[5], evG0[5];
    if (!side) {
        cudaStreamCreateWithFlags(&side, cudaStreamNonBlocking);
        cudaStreamCreateWithFlags(&s2, cudaStreamNonBlocking);
        cudaEventCreateWithFlags(&evFork, cudaEventDisableTiming);
        cudaEventCreateWithFlags(&evPre, cudaEventDisableTiming);
        for (int i = 0; i < 6; i++) cudaEventCreateWithFlags(&evH[i], cudaEventDisableTiming);
        for (int i = 0; i < 6; i++) cudaEventCreateWithFlags(&evP[i], cudaEventDisableTiming);
        for (int i = 0; i < 5; i++) cudaEventCreateWithFlags(&evA0[i], cudaEventDisableTiming);
        for (int i = 0; i < 5; i++) cudaEventCreateWithFlags(&evG0[i], cudaEventDisableTiming);
    }

    int nb256 = (n + 255) / 256;
    int eb4 = (e / 4 + 255) / 256;
    int gemm_blocks = (n + 127) / 128;
    int agg_blocks = (n * 16 + 255) / 256;
    int nchunk = (n + CHUNK - 1) / CHUNK;

    int nh = ((n / 2 + 127) / 128) * 128;            // half boundary, 128-aligned
    int aggb_h0 = (nh * 16 + 255) / 256;
    int aggb_h1 = ((n - nh) * 16 + 255) / 256;
    int gemb_h0 = nh / 128;
    int gemb_h1 = (n - nh + 127) / 128;

    // ---- fork: indeg chain on side; outdeg + GEMM L0 on main ----
    cudaEventRecord(evFork, 0);
    cudaStreamWaitEvent(side, evFork, 0);

    zero_in_kernel<<<nb256, 256, 0, side>>>(n);
    count_in_kernel<<<eb4, 256, 0, side>>>(dst, e);
    chunksum_kernel<<<nchunk, 1024, 0, side>>>(n);
    rescan_kernel<<<nchunk, 1024, 0, side>>>(n);
    csr_kernel<<<eb4, 256, 0, side>>>(src, dst, e);
    cudaEventRecord(evPre, side);

    zero_out_kernel<<<nb256, 256>>>(n);
    count_out_kernel<<<eb4, 256>>>(src, e);
    ns_kernel<<<nb256, 256>>>(n);
    gemm_pk<FIN><<<gemm_blocks, 128>>>(feats, FIN, W[0], A, nullptr, 1, 0, 0, n);

    // layer 0 aggregate: h1 = relu(nd * sum(ns[s]*t0[s]) + b0)
    cudaStreamWaitEvent(0, evPre, 0);
    aggregate_kernel<true, 1><<<agg_blocks, 256>>>(A, hb[0], b[0], 0, n);
    cudaEventRecord(evH[1], 0);

    // layers 1..4: A_l = gather_ns(h_l); h_{l+1} = relu(nd*(A_l@W_l)+b_l)
    for (int l = 1; l < 5; l++) {
        float* h_in = hb[(l - 1) % 3];
        float* h_out = hb[l % 3];

        // side: proj (+)= h_l @ Wout_{l-1}
        cudaStreamWaitEvent(side, evH[l], 0);
        gemm_pk<HID><<<gemm_blocks, 128, 0, side>>>(
            h_in, HID, Wout + (size_t)(l - 1) * HID * 64, proj, nullptr,
            1, (l > 1) ? 1 : 0, 0, n);
        cudaEventRecord(evP[l], side);

        // main: gather half0 -> A[0:nh)
        aggregate_kernel<true, 0><<<aggb_h0, 256>>>(h_in, A, nullptr, 0, nh);
        cudaEventRecord(evA0[l], 0);

        // s2: gemm_relu half0 (A rows [0,nh) -> h_out rows [0,nh))
        cudaStreamWaitEvent(s2, evA0[l], 0);
        if (l >= 3) cudaStreamWaitEvent(s2, evP[l - 2], 0);   // h_out buffer guard
        gemm_pk<HID><<<gemb_h0, 128, 0, s2>>>(
            A, HID, W[l], h_out, b[l], 2, 0, 0, nh);
        cudaEventRecord(evG0[l], s2);

        // main: gather half1 -> A[nh:n), then gemm_relu half1
        aggregate_kernel<true, 0><<<aggb_h1, 256>>>(h_in, A, nullptr, nh, n);
        if (l >= 3) cudaStreamWaitEvent(0, evP[l - 2], 0);
        gemm_pk<HID><<<gemb_h1, 128>>>(
            A, HID, W[l], h_out, b[l], 2, 0, nh, n);
        cudaStreamWaitEvent(0, evG0[l], 0);
        cudaEventRecord(evH[l + 1], 0);
    }

    // side: proj += h5 @ Wout_4
    float* h5 = hb[4 % 3];
    cudaStreamWaitEvent(side, evH[5], 0);
    gemm_pk<HID><<<gemm_blocks, 128, 0, side>>>(
        h5, HID, Wout + (size_t)4 * HID * 64, proj, nullptr, 1, 1, 0, n);
    cudaEventRecord(evP[5], side);

    // main: out = sum(proj[src]) + bout
    cudaStreamWaitEvent(0, evP[5], 0);
    aggregate_kernel<false, 2><<<agg_blocks, 256>>>(proj, out, bout, 0, n);
}